// round 2
// baseline (speedup 1.0000x reference)
#include <cuda_runtime.h>
#include <math.h>

#define NB 256
#define NC 1000
#define ND 128
#define NQ 262144
#define RPB 8

// d_out flat layout (in-order tuple concat):
//   output   [256,1000]  @ 0
//   output2  [256,1000]  @ 256000
//   features [262656,128]@ 512000   (q | k | queue)
//   labels   [262656]    @ 34131968 (lab, lab, queue_pseudo)
//   score    [256,1000]  @ 34394624
//   protos   [1000,128]  @ 34650624
static const size_t OFF_OUT   = 0;
static const size_t OFF_OUT2  = 256000;
static const size_t OFF_FEAT  = 512000;
static const size_t OFF_LAB   = 34131968;
static const size_t OFF_SCORE = 34394624;
static const size_t OFF_PROT  = 34650624;

__device__ int g_labels[NB];

// ---------------------------------------------------------------------------
// Pseudo-label: argmax_c( output[b,c] * partial_Y[b,c] ), first-occurrence tie
// (softmax/temperature are monotone -> same argmax as raw masked logits)
// ---------------------------------------------------------------------------
__global__ void argmax_kernel(const float* __restrict__ out1,
                              const float* __restrict__ maskY,
                              float* __restrict__ lab_out) {
    int b = blockIdx.x;
    const float* o = out1 + (size_t)b * NC;
    const float* m = maskY + (size_t)b * NC;
    float best = -INFINITY;
    int   bidx = NC;
    for (int c = threadIdx.x; c < NC; c += blockDim.x) {
        float v = o[c] * m[c];
        if (v > best) { best = v; bidx = c; }   // strict > keeps first occurrence
    }
    __shared__ float sv[256];
    __shared__ int   si[256];
    sv[threadIdx.x] = best; si[threadIdx.x] = bidx;
    __syncthreads();
    for (int s = 128; s > 0; s >>= 1) {
        if (threadIdx.x < s) {
            float ov = sv[threadIdx.x + s];
            int   oi = si[threadIdx.x + s];
            if (ov > sv[threadIdx.x] ||
                (ov == sv[threadIdx.x] && oi < si[threadIdx.x])) {
                sv[threadIdx.x] = ov; si[threadIdx.x] = oi;
            }
        }
        __syncthreads();
    }
    if (threadIdx.x == 0) {
        int lab = si[0];
        g_labels[b]       = lab;
        lab_out[b]        = (float)lab;   // pseudo_labels[0:B]
        lab_out[NB + b]   = (float)lab;   // pseudo_labels[B:2B]
    }
}

// ---------------------------------------------------------------------------
// score_prot = softmax(q @ protos^T) — 8 q-rows per block to amortize
// prototype reads through L2. protos is read PRE-update (input buffer).
// ---------------------------------------------------------------------------
__global__ void score_kernel(const float* __restrict__ q,
                             const float* __restrict__ protos,
                             float* __restrict__ score) {
    __shared__ float qs[RPB][ND];
    int b0 = blockIdx.x * RPB;
    for (int i = threadIdx.x; i < RPB * ND; i += blockDim.x)
        qs[i >> 7][i & 127] = q[(size_t)b0 * ND + i];
    __syncthreads();

    float acc[4][RPB];
#pragma unroll
    for (int it = 0; it < 4; it++)
#pragma unroll
        for (int r = 0; r < RPB; r++) acc[it][r] = -INFINITY;

#pragma unroll
    for (int it = 0; it < 4; it++) {
        int c = threadIdx.x + it * 256;
        if (c < NC) {
            float a[RPB];
#pragma unroll
            for (int r = 0; r < RPB; r++) a[r] = 0.f;
            const float4* prow = (const float4*)(protos + (size_t)c * ND);
#pragma unroll 4
            for (int d4 = 0; d4 < ND / 4; d4++) {
                float4 p = prow[d4];
#pragma unroll
                for (int r = 0; r < RPB; r++) {
                    a[r] += p.x * qs[r][d4 * 4 + 0] + p.y * qs[r][d4 * 4 + 1]
                          + p.z * qs[r][d4 * 4 + 2] + p.w * qs[r][d4 * 4 + 3];
                }
            }
#pragma unroll
            for (int r = 0; r < RPB; r++) acc[it][r] = a[r];
        }
    }

    int lane = threadIdx.x & 31, wid = threadIdx.x >> 5;
    __shared__ float wred[8][RPB];

    // row max
    float rowmax[RPB];
    {
        float m[RPB];
#pragma unroll
        for (int r = 0; r < RPB; r++) {
            float v = fmaxf(fmaxf(acc[0][r], acc[1][r]),
                            fmaxf(acc[2][r], acc[3][r]));
#pragma unroll
            for (int off = 16; off > 0; off >>= 1)
                v = fmaxf(v, __shfl_xor_sync(0xffffffffu, v, off));
            m[r] = v;
        }
        if (lane == 0)
#pragma unroll
            for (int r = 0; r < RPB; r++) wred[wid][r] = m[r];
        __syncthreads();
#pragma unroll
        for (int r = 0; r < RPB; r++) {
            float v = wred[0][r];
#pragma unroll
            for (int w = 1; w < 8; w++) v = fmaxf(v, wred[w][r]);
            rowmax[r] = v;
        }
        __syncthreads();
    }

    // exp + row sum
    float sm[RPB];
#pragma unroll
    for (int r = 0; r < RPB; r++) sm[r] = 0.f;
#pragma unroll
    for (int it = 0; it < 4; it++) {
        int c = threadIdx.x + it * 256;
#pragma unroll
        for (int r = 0; r < RPB; r++) {
            float e = (c < NC) ? expf(acc[it][r] - rowmax[r]) : 0.f;
            acc[it][r] = e;
            sm[r] += e;
        }
    }
    float rowsum[RPB];
    {
#pragma unroll
        for (int r = 0; r < RPB; r++) {
            float s = sm[r];
#pragma unroll
            for (int off = 16; off > 0; off >>= 1)
                s += __shfl_xor_sync(0xffffffffu, s, off);
            sm[r] = s;
        }
        if (lane == 0)
#pragma unroll
            for (int r = 0; r < RPB; r++) wred[wid][r] = sm[r];
        __syncthreads();
#pragma unroll
        for (int r = 0; r < RPB; r++) {
            float s = 0.f;
#pragma unroll
            for (int w = 0; w < 8; w++) s += wred[w][r];
            rowsum[r] = s;
        }
    }

    // write softmax
#pragma unroll
    for (int it = 0; it < 4; it++) {
        int c = threadIdx.x + it * 256;
        if (c < NC) {
#pragma unroll
            for (int r = 0; r < RPB; r++)
                score[(size_t)(b0 + r) * NC + c] = acc[it][r] / rowsum[r];
        }
    }
}

// ---------------------------------------------------------------------------
// EMA scatter + L2 normalize. Sequential order only matters per label, so run
// the 256-step scan independently per label row (1000 blocks x 128 threads).
// Reads the PRE-update prototypes input; writes only to d_out.
// ---------------------------------------------------------------------------
__global__ void ema_kernel(const float* __restrict__ protos,
                           const float* __restrict__ q,
                           float* __restrict__ out) {
    int c = blockIdx.x;
    int d = threadIdx.x;  // 128 threads
    __shared__ int lab[NB];
    for (int i = d; i < NB; i += 128) lab[i] = g_labels[i];
    __syncthreads();

    float val = protos[(size_t)c * ND + d];
    for (int b = 0; b < NB; b++) {
        if (lab[b] == c)
            val = val * 0.99f + 0.01f * q[(size_t)b * ND + d];
    }

    float ss = val * val;
#pragma unroll
    for (int off = 16; off > 0; off >>= 1)
        ss += __shfl_xor_sync(0xffffffffu, ss, off);
    __shared__ float s4[4];
    int lane = d & 31, wid = d >> 5;
    if (lane == 0) s4[wid] = ss;
    __syncthreads();
    float tot = s4[0] + s4[1] + s4[2] + s4[3];
    float denom = fmaxf(sqrtf(tot), 1e-12f);
    out[(size_t)c * ND + d] = val / denom;
}

// ---------------------------------------------------------------------------
extern "C" void kernel_launch(void* const* d_in, const int* in_sizes, int n_in,
                              void* d_out, int out_size) {
    const float* q            = (const float*)d_in[0];
    const float* k            = (const float*)d_in[1];
    const float* out1         = (const float*)d_in[2];
    const float* out2         = (const float*)d_in[3];
    const float* partial_Y    = (const float*)d_in[4];
    const float* protos       = (const float*)d_in[5];
    const float* queue        = (const float*)d_in[6];
    const float* queue_pseudo = (const float*)d_in[7];
    float* o = (float*)d_out;

    // Pure passthrough / concat copies (D2D async — graph-capturable).
    cudaMemcpyAsync(o + OFF_OUT,  out1, sizeof(float) * (size_t)NB * NC,
                    cudaMemcpyDeviceToDevice);
    cudaMemcpyAsync(o + OFF_OUT2, out2, sizeof(float) * (size_t)NB * NC,
                    cudaMemcpyDeviceToDevice);
    cudaMemcpyAsync(o + OFF_FEAT, q, sizeof(float) * (size_t)NB * ND,
                    cudaMemcpyDeviceToDevice);
    cudaMemcpyAsync(o + OFF_FEAT + (size_t)NB * ND, k,
                    sizeof(float) * (size_t)NB * ND, cudaMemcpyDeviceToDevice);
    cudaMemcpyAsync(o + OFF_FEAT + 2 * (size_t)NB * ND, queue,
                    sizeof(float) * (size_t)NQ * ND, cudaMemcpyDeviceToDevice);
    cudaMemcpyAsync(o + OFF_LAB + 2 * NB, queue_pseudo,
                    sizeof(float) * (size_t)NQ, cudaMemcpyDeviceToDevice);

    argmax_kernel<<<NB, 256>>>(out1, partial_Y, o + OFF_LAB);
    score_kernel<<<NB / RPB, 256>>>(q, protos, o + OFF_SCORE);
    ema_kernel<<<NC, ND>>>(protos, q, o + OFF_PROT);
}

// round 3
// speedup vs baseline: 1.2260x; 1.2260x over previous
#include <cuda_runtime.h>
#include <math.h>

#define NB 256
#define NC 1000
#define ND 128
#define NQ 262144
#define RPB 8

// d_out flat layout (in-order tuple concat):
//   output   [256,1000]  @ 0
//   output2  [256,1000]  @ 256000
//   features [262656,128]@ 512000   (q | k | queue)
//   labels   [262656]    @ 34131968 (lab, lab, queue_pseudo)
//   score    [256,1000]  @ 34394624
//   protos   [1000,128]  @ 34650624
static const size_t OFF_OUT   = 0;
static const size_t OFF_OUT2  = 256000;
static const size_t OFF_FEAT  = 512000;
static const size_t OFF_LAB   = 34131968;
static const size_t OFF_SCORE = 34394624;
static const size_t OFF_PROT  = 34650624;

#define SCORE_BLOCKS (NB / RPB)        /* 32  */
#define EMA_BLOCKS   (NC / 2)          /* 500 */
#define COPY_BLOCKS  2048
#define TOTAL_BLOCKS (SCORE_BLOCKS + EMA_BLOCKS + COPY_BLOCKS)

// float4 segment sizes for the fused copy
#define SEG_QUEUE  ((size_t)NQ * ND / 4)   /* 8388608 */
#define SEG_OUT    ((size_t)NB * NC / 4)   /* 64000   */
#define SEG_QK     ((size_t)NB * ND / 4)   /* 8192    */
#define SEG_QP     ((size_t)NQ / 4)        /* 65536   */
#define TOTAL_F4   (SEG_QUEUE + 2*SEG_OUT + 2*SEG_QK + SEG_QP)

__device__ int g_labels[NB];

// ---------------------------------------------------------------------------
// Pseudo-label argmax: warp per row, pure shuffle reduction.
// argmax_c( output[b,c] * partial_Y[b,c] ), first-occurrence tie-break.
// ---------------------------------------------------------------------------
__global__ void __launch_bounds__(256) argmax_kernel(
        const float* __restrict__ out1,
        const float* __restrict__ maskY,
        float* __restrict__ lab_out) {
    int wid  = threadIdx.x >> 5;
    int lane = threadIdx.x & 31;
    int b = blockIdx.x * 8 + wid;           // 32 blocks x 8 warps = 256 rows
    const float* o = out1  + (size_t)b * NC;
    const float* m = maskY + (size_t)b * NC;

    float best = -INFINITY;
    int   bidx = NC;
    for (int c = lane; c < NC; c += 32) {   // ascending -> per-lane first occ.
        float v = o[c] * m[c];
        if (v > best) { best = v; bidx = c; }
    }
#pragma unroll
    for (int off = 16; off > 0; off >>= 1) {
        float ov = __shfl_xor_sync(0xffffffffu, best, off);
        int   oi = __shfl_xor_sync(0xffffffffu, bidx, off);
        if (ov > best || (ov == best && oi < bidx)) { best = ov; bidx = oi; }
    }
    if (lane == 0) {
        g_labels[b]     = bidx;
        lab_out[b]      = (float)bidx;
        lab_out[NB + b] = (float)bidx;
    }
}

// ---------------------------------------------------------------------------
// Mega kernel: score (32 blocks) | ema (500 blocks) | fused copy (2048 blocks)
// ---------------------------------------------------------------------------
__global__ void __launch_bounds__(256) mega_kernel(
        const float* __restrict__ q,
        const float* __restrict__ k,
        const float* __restrict__ out1,
        const float* __restrict__ out2,
        const float* __restrict__ protos,
        const float* __restrict__ queue,
        const float* __restrict__ queue_pseudo,
        float* __restrict__ o) {
    int bid = blockIdx.x;
    int tid = threadIdx.x;

    if (bid < SCORE_BLOCKS) {
        // ------------------ score_prot = softmax(q @ protos^T) -------------
        float* score = o + OFF_SCORE;
        __shared__ float qs[RPB][ND];
        __shared__ float wred[8][RPB];
        int b0 = bid * RPB;
        for (int i = tid; i < RPB * ND; i += 256)
            qs[i >> 7][i & 127] = q[(size_t)b0 * ND + i];
        __syncthreads();

        float acc[4][RPB];
#pragma unroll
        for (int it = 0; it < 4; it++)
#pragma unroll
            for (int r = 0; r < RPB; r++) acc[it][r] = -INFINITY;

#pragma unroll
        for (int it = 0; it < 4; it++) {
            int c = tid + it * 256;
            if (c < NC) {
                float a[RPB];
#pragma unroll
                for (int r = 0; r < RPB; r++) a[r] = 0.f;
                const float4* prow = (const float4*)(protos + (size_t)c * ND);
#pragma unroll 4
                for (int d4 = 0; d4 < ND / 4; d4++) {
                    float4 p = prow[d4];
#pragma unroll
                    for (int r = 0; r < RPB; r++) {
                        a[r] += p.x * qs[r][d4*4+0] + p.y * qs[r][d4*4+1]
                              + p.z * qs[r][d4*4+2] + p.w * qs[r][d4*4+3];
                    }
                }
#pragma unroll
                for (int r = 0; r < RPB; r++) acc[it][r] = a[r];
            }
        }

        int lane = tid & 31, wd = tid >> 5;
        // row max
        float rowmax[RPB];
        {
            float mx[RPB];
#pragma unroll
            for (int r = 0; r < RPB; r++) {
                float v = fmaxf(fmaxf(acc[0][r], acc[1][r]),
                                fmaxf(acc[2][r], acc[3][r]));
#pragma unroll
                for (int off = 16; off > 0; off >>= 1)
                    v = fmaxf(v, __shfl_xor_sync(0xffffffffu, v, off));
                mx[r] = v;
            }
            if (lane == 0)
#pragma unroll
                for (int r = 0; r < RPB; r++) wred[wd][r] = mx[r];
            __syncthreads();
#pragma unroll
            for (int r = 0; r < RPB; r++) {
                float v = wred[0][r];
#pragma unroll
                for (int w = 1; w < 8; w++) v = fmaxf(v, wred[w][r]);
                rowmax[r] = v;
            }
            __syncthreads();
        }
        // exp + sum
        float sm[RPB];
#pragma unroll
        for (int r = 0; r < RPB; r++) sm[r] = 0.f;
#pragma unroll
        for (int it = 0; it < 4; it++) {
            int c = tid + it * 256;
#pragma unroll
            for (int r = 0; r < RPB; r++) {
                float e = (c < NC) ? expf(acc[it][r] - rowmax[r]) : 0.f;
                acc[it][r] = e;
                sm[r] += e;
            }
        }
        float rowsum[RPB];
        {
#pragma unroll
            for (int r = 0; r < RPB; r++) {
                float s = sm[r];
#pragma unroll
                for (int off = 16; off > 0; off >>= 1)
                    s += __shfl_xor_sync(0xffffffffu, s, off);
                sm[r] = s;
            }
            if (lane == 0)
#pragma unroll
                for (int r = 0; r < RPB; r++) wred[wd][r] = sm[r];
            __syncthreads();
#pragma unroll
            for (int r = 0; r < RPB; r++) {
                float s = 0.f;
#pragma unroll
                for (int w = 0; w < 8; w++) s += wred[w][r];
                rowsum[r] = s;
            }
        }
#pragma unroll
        for (int it = 0; it < 4; it++) {
            int c = tid + it * 256;
            if (c < NC) {
#pragma unroll
                for (int r = 0; r < RPB; r++)
                    score[(size_t)(b0 + r) * NC + c] = acc[it][r] / rowsum[r];
            }
        }
    } else if (bid < SCORE_BLOCKS + EMA_BLOCKS) {
        // ------------------ EMA scatter + L2 normalize (2 labels/block) ----
        int part = bid - SCORE_BLOCKS;
        int c = part * 2 + (tid >> 7);   // two label-rows per block
        int d = tid & 127;
        __shared__ int   lab[NB];
        __shared__ float s8[8];
        for (int i = tid; i < NB; i += 256) lab[i] = g_labels[i];
        __syncthreads();

        float val = protos[(size_t)c * ND + d];
        for (int b = 0; b < NB; b++) {
            if (lab[b] == c)
                val = val * 0.99f + 0.01f * q[(size_t)b * ND + d];
        }
        float ss = val * val;
#pragma unroll
        for (int off = 16; off > 0; off >>= 1)
            ss += __shfl_xor_sync(0xffffffffu, ss, off);
        int lane = tid & 31, wd = tid >> 5;  // wd 0..7; wd/4 = row half
        if (lane == 0) s8[wd] = ss;
        __syncthreads();
        int h = tid >> 7;
        float tot = s8[h*4+0] + s8[h*4+1] + s8[h*4+2] + s8[h*4+3];
        float denom = fmaxf(sqrtf(tot), 1e-12f);
        o[OFF_PROT + (size_t)c * ND + d] = val / denom;
    } else {
        // ------------------ fused concat copies (float4, streaming) --------
        size_t idx = (size_t)(bid - SCORE_BLOCKS - EMA_BLOCKS) * 256 + tid;
        const size_t stride = (size_t)COPY_BLOCKS * 256;

        const float4* qu4  = (const float4*)queue;
        const float4* o14  = (const float4*)out1;
        const float4* o24  = (const float4*)out2;
        const float4* q4   = (const float4*)q;
        const float4* k4   = (const float4*)k;
        const float4* qp4  = (const float4*)queue_pseudo;
        float4* d_qu = (float4*)(o + OFF_FEAT + 2 * (size_t)NB * ND);
        float4* d_o1 = (float4*)(o + OFF_OUT);
        float4* d_o2 = (float4*)(o + OFF_OUT2);
        float4* d_q  = (float4*)(o + OFF_FEAT);
        float4* d_k  = (float4*)(o + OFF_FEAT + (size_t)NB * ND);
        float4* d_qp = (float4*)(o + OFF_LAB + 2 * NB);

        for (; idx < TOTAL_F4; idx += stride) {
            size_t i = idx;
            if (i < SEG_QUEUE) { __stcs(&d_qu[i], __ldcs(&qu4[i])); continue; }
            i -= SEG_QUEUE;
            if (i < SEG_OUT)   { __stcs(&d_o1[i], __ldcs(&o14[i])); continue; }
            i -= SEG_OUT;
            if (i < SEG_OUT)   { __stcs(&d_o2[i], __ldcs(&o24[i])); continue; }
            i -= SEG_OUT;
            if (i < SEG_QK)    { __stcs(&d_q[i],  __ldcs(&q4[i]));  continue; }
            i -= SEG_QK;
            if (i < SEG_QK)    { __stcs(&d_k[i],  __ldcs(&k4[i]));  continue; }
            i -= SEG_QK;
            __stcs(&d_qp[i], __ldcs(&qp4[i]));
        }
    }
}

// ---------------------------------------------------------------------------
extern "C" void kernel_launch(void* const* d_in, const int* in_sizes, int n_in,
                              void* d_out, int out_size) {
    const float* q            = (const float*)d_in[0];
    const float* k            = (const float*)d_in[1];
    const float* out1         = (const float*)d_in[2];
    const float* out2         = (const float*)d_in[3];
    const float* partial_Y    = (const float*)d_in[4];
    const float* protos       = (const float*)d_in[5];
    const float* queue        = (const float*)d_in[6];
    const float* queue_pseudo = (const float*)d_in[7];
    float* o = (float*)d_out;

    argmax_kernel<<<32, 256>>>(out1, partial_Y, o + OFF_LAB);
    mega_kernel<<<TOTAL_BLOCKS, 256>>>(q, k, out1, out2, protos,
                                       queue, queue_pseudo, o);
}